// round 6
// baseline (speedup 1.0000x reference)
#include <cuda_runtime.h>
#include <math.h>
#include <stdint.h>

// Problem dims (fixed by the dataset)
#define NN 1000
#define PP 50000
#define ZZ 20
#define LL 10

#define CLUSTER 8
#define CH (PP / CLUSTER)      // 6250 columns per CTA
#define CH2 (CH / 2)           // 3125 float2 per CTA
#define NT 1024                // threads per CTA
#define NCH 4                  // n-chunks for ZtX GEMM
#define NCHN (NN / NCH)        // 250

// Scratch (static device globals; no allocation)
__device__ float g_W[ZZ * PP];           // 4 MB  collapsed loadings
__device__ float g_ZtX[ZZ * PP];         // 4 MB
__device__ float g_ZtXp[NCH * ZZ * PP];  // 16 MB partials

// ---------------------------------------------------------------------------
// Kernel 1: W[k,i] = sum_l mean_w[l,k,i] * alpha[l,k,i]
// ---------------------------------------------------------------------------
__global__ void winit_kernel(const float* __restrict__ mw,
                             const float* __restrict__ al) {
    int idx = blockIdx.x * blockDim.x + threadIdx.x;
    if (idx >= ZZ * PP) return;
    float s = 0.f;
#pragma unroll
    for (int l = 0; l < LL; l++)
        s += mw[l * (ZZ * PP) + idx] * al[l * (ZZ * PP) + idx];
    g_W[idx] = s;
}

// ---------------------------------------------------------------------------
// Kernel 2: ZtX partials. grid = (ceil(P/4/256), NCH). Each thread: 4 columns,
// 250 rows of data, mean_z chunk staged in SMEM.
// ---------------------------------------------------------------------------
__global__ __launch_bounds__(256) void ztx_partial_kernel(
    const float* __restrict__ data, const float* __restrict__ mz) {
    __shared__ float sz[NCHN * ZZ];  // 250*20 floats = 20 KB
    int c = blockIdx.y;
    for (int t = threadIdx.x; t < NCHN * ZZ; t += blockDim.x)
        sz[t] = mz[c * (NCHN * ZZ) + t];
    __syncthreads();

    int g = blockIdx.x * blockDim.x + threadIdx.x;
    if (g >= PP / 4) return;
    int j = g * 4;

    float4 acc[ZZ];
#pragma unroll
    for (int k = 0; k < ZZ; k++) acc[k] = make_float4(0.f, 0.f, 0.f, 0.f);

    const float* dp = data + (size_t)c * NCHN * PP + j;
    for (int nn = 0; nn < NCHN; nn++) {
        float4 d = *(const float4*)(dp + (size_t)nn * PP);
#pragma unroll
        for (int k = 0; k < ZZ; k++) {
            float zv = sz[nn * ZZ + k];
            acc[k].x += d.x * zv;
            acc[k].y += d.y * zv;
            acc[k].z += d.z * zv;
            acc[k].w += d.w * zv;
        }
    }
#pragma unroll
    for (int k = 0; k < ZZ; k++)
        *(float4*)&g_ZtXp[(size_t)c * (ZZ * PP) + k * PP + j] = acc[k];
}

__global__ void ztx_reduce_kernel() {
    int idx = blockIdx.x * blockDim.x + threadIdx.x;
    if (idx >= ZZ * PP) return;
    float s = 0.f;
#pragma unroll
    for (int c = 0; c < NCH; c++) s += g_ZtXp[c * (ZZ * PP) + idx];
    g_ZtX[idx] = s;
}

// ---------------------------------------------------------------------------
// Cluster helpers
// ---------------------------------------------------------------------------
__device__ __forceinline__ unsigned smem_u32(const void* p) {
    return (unsigned)__cvta_generic_to_shared(p);
}
__device__ __forceinline__ void remote_st_f32(unsigned laddr, unsigned rank, float v) {
    unsigned r;
    asm volatile("mapa.shared::cluster.u32 %0, %1, %2;" : "=r"(r) : "r"(laddr), "r"(rank));
    asm volatile("st.shared::cluster.f32 [%0], %1;" :: "r"(r), "f"(v) : "memory");
}
__device__ __forceinline__ void cluster_sync_() {
    asm volatile("barrier.cluster.arrive.aligned;" ::: "memory");
    asm volatile("barrier.cluster.wait.aligned;" ::: "memory");
}
__device__ __forceinline__ unsigned ctarank() {
    unsigned r;
    asm("mov.u32 %0, %%cluster_ctarank;" : "=r"(r));
    return r;
}

__device__ __forceinline__ float blkmax(float v, float* sRed) {
#pragma unroll
    for (int o = 16; o; o >>= 1) v = fmaxf(v, __shfl_xor_sync(0xffffffffu, v, o));
    int w = threadIdx.x >> 5, lane = threadIdx.x & 31;
    __syncthreads();
    if (!lane) sRed[w] = v;
    __syncthreads();
    if (!w) {
        v = sRed[lane];
#pragma unroll
        for (int o = 16; o; o >>= 1) v = fmaxf(v, __shfl_xor_sync(0xffffffffu, v, o));
        if (!lane) sRed[0] = v;
    }
    __syncthreads();
    return sRed[0];
}

__device__ __forceinline__ float blksum(float v, float* sRed) {
#pragma unroll
    for (int o = 16; o; o >>= 1) v += __shfl_xor_sync(0xffffffffu, v, o);
    int w = threadIdx.x >> 5, lane = threadIdx.x & 31;
    __syncthreads();
    if (!lane) sRed[w] = v;
    __syncthreads();
    if (!w) {
        v = sRed[lane];
#pragma unroll
        for (int o = 16; o; o >>= 1) v += __shfl_xor_sync(0xffffffffu, v, o);
        if (!lane) sRed[0] = v;
    }
    __syncthreads();
    return sRed[0];
}

// ---------------------------------------------------------------------------
// Kernel 3: sequential CAVI over (k, l). One 8-CTA cluster; each CTA owns
// CH=6250 columns. Only cross-CTA coupling: softmax (max, sum) per step ->
// exactly ONE cluster barrier per (k,l), partials double-buffered by parity.
// All column sweeps are float2-vectorized (CH even; all bases 8B-aligned).
// SMEM per CTA: D, RtZk, log_pi, E, s/e  (5 * 25 KB) + reduce/publish scratch.
// ---------------------------------------------------------------------------
#define SMEM_FLOATS (5 * CH + 32 + 32)
#define SMEM_BYTES (SMEM_FLOATS * 4)

__global__ void __cluster_dims__(CLUSTER, 1, 1) __launch_bounds__(NT, 1)
cavi_kernel(const float* __restrict__ mzz, const float* __restrict__ mw_in,
            const float* __restrict__ a_in, const float* __restrict__ tau_p,
            const float* __restrict__ tau0, const float* __restrict__ pi,
            float* __restrict__ out_mw, float* __restrict__ out_vw,
            float* __restrict__ out_a) {
    extern __shared__ float sm[];
    float2* sD = (float2*)sm;                  // [CH2] D = RtZk - Ez*Wk
    float2* sR = (float2*)(sm + CH);           // [CH2] RtZk (constant within k)
    float2* sLP = (float2*)(sm + 2 * CH);      // [CH2] log(pi[k])
    float2* sE = (float2*)(sm + 3 * CH);       // [CH2] E_RtZk of current l
    float2* sS = (float2*)(sm + 4 * CH);       // [CH2] s, then exp(s - m_r)
    float* sRed = sm + 5 * CH;                 // [32] block reduce scratch
    float* sPub = sm + 5 * CH + 32;            // [2][8][2] publish slots

    const unsigned rank = ctarank();
    const int base = rank * CH;
    const int tid = threadIdx.x;
    const int lane = tid & 31;
    const float tau = __ldg(tau_p);

    int step = 0;
    for (int k = 0; k < ZZ; k++) {
        float mrow[ZZ];
#pragma unroll
        for (int j = 0; j < ZZ; j++) mrow[j] = __ldg(&mzz[k * ZZ + j]);
        const float Ez = mrow[k];
        const float invEz = 1.f / Ez;

        // Prologue: RtZk, D, log_pi cache (column-local, no cross-CTA deps)
        {
            const float2* ztx2 = (const float2*)&g_ZtX[k * PP + base];
            const float2* pi2 = (const float2*)(pi + (size_t)k * PP + base);
            for (int i = tid; i < CH2; i += NT) {
                float2 acc = ztx2[i];
                float2 wkv = make_float2(0.f, 0.f);
#pragma unroll
                for (int j = 0; j < ZZ; j++) {
                    float2 w = ((const float2*)&g_W[j * PP + base])[i];
                    if (j == k) {
                        wkv = w;
                    } else {
                        acc.x -= mrow[j] * w.x;
                        acc.y -= mrow[j] * w.y;
                    }
                }
                sR[i] = acc;
                sD[i] = make_float2(acc.x - Ez * wkv.x, acc.y - Ez * wkv.y);
                float2 p = __ldg(&pi2[i]);
                sLP[i] = make_float2(__logf(p.x), __logf(p.y));
            }
        }
        __syncthreads();

        const float s2 = 1.f / (Ez * tau);
        const float l_s2 = __logf(s2);

        for (int l = 0; l < LL; l++, step++) {
            const float t0 = __ldg(&tau0[l * ZZ + k]);
            const float s0inv = 1.f / t0;
            const float s2p = s2 + s0inv;
            const float c0 = 0.5f * (l_s2 - __logf(s2p));
            const float c1 = 0.5f * (s0inv / s2p) * (tau * invEz);  // * zs_scale^2
            const float varn = 1.f / (tau * Ez + t0);
            const float tv = tau * varn;

            const float2* mwp = (const float2*)(mw_in + ((size_t)l * ZZ + k) * PP + base);
            const float2* ap = (const float2*)(a_in + ((size_t)l * ZZ + k) * PP + base);

            // sweep 1: E, s, local max
            float lmax = -INFINITY;
            for (int i = tid; i < CH2; i += NT) {
                float2 d = sD[i];
                float2 m2 = __ldg(&mwp[i]);
                float2 a2 = __ldg(&ap[i]);
                float Ex = fmaf(Ez, m2.x * a2.x, d.x);
                float Ey = fmaf(Ez, m2.y * a2.y, d.y);
                sE[i] = make_float2(Ex, Ey);
                float2 lp = sLP[i];
                float sx = fmaf(c1 * Ex, Ex, lp.x + c0);
                float sy = fmaf(c1 * Ey, Ey, lp.y + c0);
                sS[i] = make_float2(sx, sy);
                lmax = fmaxf(lmax, fmaxf(sx, sy));
            }
            float m_r = blkmax(lmax, sRed);

            // sweep 2: e = exp(s - m_r), local sum (one exp per element)
            float lsum = 0.f;
            for (int i = tid; i < CH2; i += NT) {
                float2 s = sS[i];
                float ex = __expf(s.x - m_r);
                float ey = __expf(s.y - m_r);
                sS[i] = make_float2(ex, ey);
                lsum += ex + ey;
            }
            float S_r = blksum(lsum, sRed);

            // publish (m_r, S_r) to every CTA's slot [par][rank], 1 cluster sync
            int par = step & 1;
            if (tid == 0) {
                unsigned la = smem_u32(&sPub[par * 16 + rank * 2]);
#pragma unroll
                for (unsigned r = 0; r < CLUSTER; r++) {
                    remote_st_f32(la, r, m_r);
                    remote_st_f32(la + 4, r, S_r);
                }
            }
            cluster_sync_();

            // combine (per-warp via shuffles; all local SMEM reads)
            float mr_o = -INFINITY, sr_o = 0.f;
            if (lane < CLUSTER) {
                mr_o = sPub[par * 16 + lane * 2];
                sr_o = sPub[par * 16 + lane * 2 + 1];
            }
            float M = mr_o;
#pragma unroll
            for (int o = 16; o; o >>= 1) M = fmaxf(M, __shfl_xor_sync(0xffffffffu, M, o));
            float contrib = (lane < CLUSTER) ? sr_o * __expf(mr_o - M) : 0.f;
#pragma unroll
            for (int o = 16; o; o >>= 1) contrib += __shfl_xor_sync(0xffffffffu, contrib, o);
            const float scale = __expf(m_r - M) / contrib;

            // phase 3: alpha, mean, D update, streaming output writes
            float2* omw = (float2*)(out_mw + ((size_t)l * ZZ + k) * PP + base);
            float2* oa = (float2*)(out_a + ((size_t)l * ZZ + k) * PP + base);
            for (int i = tid; i < CH2; i += NT) {
                float2 e = sS[i];
                float anx = e.x * scale;
                float any = e.y * scale;
                float2 E = sE[i];
                float mnx = tv * E.x;
                float mny = tv * E.y;
                __stcs(&omw[i], make_float2(mnx, mny));
                __stcs(&oa[i], make_float2(anx, any));
                sD[i] = make_float2(fmaf(-Ez, mnx * anx, E.x),
                                    fmaf(-Ez, mny * any, E.y));
            }
            if (rank == 0 && tid == 0) out_vw[l * ZZ + k] = varn;
        }

        // epilogue: W[k] = (RtZk - D)/Ez  (own columns only; next-k prologue
        // reads only own columns -> per-CTA coherence, no cross-CTA sync)
        {
            float2* gw2 = (float2*)&g_W[k * PP + base];
            for (int i = tid; i < CH2; i += NT) {
                float2 r = sR[i];
                float2 d = sD[i];
                gw2[i] = make_float2((r.x - d.x) * invEz, (r.y - d.y) * invEz);
            }
        }
        __syncthreads();
    }
}

// ---------------------------------------------------------------------------
// Launch
// ---------------------------------------------------------------------------
extern "C" void kernel_launch(void* const* d_in, const int* in_sizes, int n_in,
                              void* d_out, int out_size) {
    const float* data = (const float*)d_in[0];
    const float* mz = (const float*)d_in[1];
    const float* mzz = (const float*)d_in[2];
    const float* mw = (const float*)d_in[3];
    // d_in[4] = var_w (unused: fully overwritten)
    const float* alpha = (const float*)d_in[5];
    const float* tau = (const float*)d_in[6];
    const float* tau0 = (const float*)d_in[7];
    const float* pi = (const float*)d_in[8];

    float* out = (float*)d_out;
    float* out_mw = out;                              // [L,Z,P]
    float* out_vw = out + (size_t)LL * ZZ * PP;       // [L,Z]
    float* out_a = out_vw + LL * ZZ;                  // [L,Z,P]

    winit_kernel<<<(ZZ * PP + 255) / 256, 256>>>(mw, alpha);

    dim3 g2((PP / 4 + 255) / 256, NCH);
    ztx_partial_kernel<<<g2, 256>>>(data, mz);
    ztx_reduce_kernel<<<(ZZ * PP + 255) / 256, 256>>>();

    cudaFuncSetAttribute(cavi_kernel, cudaFuncAttributeMaxDynamicSharedMemorySize,
                         SMEM_BYTES);
    cavi_kernel<<<CLUSTER, NT, SMEM_BYTES>>>(mzz, mw, alpha, tau, tau0, pi,
                                             out_mw, out_vw, out_a);
}

// round 9
// speedup vs baseline: 1.6319x; 1.6319x over previous
#include <cuda_runtime.h>
#include <math.h>
#include <stdint.h>

// Problem dims (fixed by the dataset)
#define NN 1000
#define PP 50000
#define ZZ 20
#define LL 10

// Persistent grid for the sequential CAVI kernel
#define NC 148                 // CTAs == min(SM count); all co-resident
#define NT 352                 // threads per CTA (11 warps)
#define NWARP (NT / 32)        // 11
#define CH 338                 // columns per CTA: 148*338 = 50024 >= 50000

// GEMM config
#define NCH 8                  // n-chunks for ZtX GEMM
#define NCHN (NN / NCH)        // 125

// Scratch (static device globals; no allocation)
__device__ float g_ZtX[ZZ * PP];                 // 4 MB
__device__ float g_ZtXp[NCH * ZZ * PP];          // 32 MB partials
__device__ float2 g_part[2][NC];                 // per-CTA (m, S) partials, dbl-buffered
__device__ unsigned g_cnt;                       // monotonic arrival counter
__device__ unsigned g_phase;                     // released barrier index

// ---------------------------------------------------------------------------
// Barrier state reset (runs first in the graph each launch)
// ---------------------------------------------------------------------------
__global__ void reset_kernel() {
    g_cnt = 0;
    g_phase = 0;
}

// ---------------------------------------------------------------------------
// ZtX GEMM: partials over n-chunks, then reduce.
// ---------------------------------------------------------------------------
__global__ __launch_bounds__(256) void ztx_partial_kernel(
    const float* __restrict__ data, const float* __restrict__ mz) {
    __shared__ float sz[NCHN * ZZ];  // 125*20 floats = 10 KB
    int c = blockIdx.y;
    for (int t = threadIdx.x; t < NCHN * ZZ; t += blockDim.x)
        sz[t] = mz[c * (NCHN * ZZ) + t];
    __syncthreads();

    int g = blockIdx.x * blockDim.x + threadIdx.x;
    if (g >= PP / 4) return;
    int j = g * 4;

    float4 acc[ZZ];
#pragma unroll
    for (int k = 0; k < ZZ; k++) acc[k] = make_float4(0.f, 0.f, 0.f, 0.f);

    const float* dp = data + (size_t)c * NCHN * PP + j;
    for (int nn = 0; nn < NCHN; nn++) {
        float4 d = *(const float4*)(dp + (size_t)nn * PP);
#pragma unroll
        for (int k = 0; k < ZZ; k++) {
            float zv = sz[nn * ZZ + k];
            acc[k].x += d.x * zv;
            acc[k].y += d.y * zv;
            acc[k].z += d.z * zv;
            acc[k].w += d.w * zv;
        }
    }
#pragma unroll
    for (int k = 0; k < ZZ; k++)
        *(float4*)&g_ZtXp[(size_t)c * (ZZ * PP) + k * PP + j] = acc[k];
}

__global__ void ztx_reduce_kernel() {
    int idx = blockIdx.x * blockDim.x + threadIdx.x;
    if (idx >= ZZ * PP) return;
    float s = 0.f;
#pragma unroll
    for (int c = 0; c < NCH; c++) s += g_ZtXp[c * (ZZ * PP) + idx];
    g_ZtX[idx] = s;
}

// ---------------------------------------------------------------------------
// Release/acquire helpers for the grid barrier
// ---------------------------------------------------------------------------
__device__ __forceinline__ unsigned ld_acquire(const unsigned* p) {
    unsigned v;
    asm volatile("ld.global.acquire.gpu.u32 %0, [%1];" : "=r"(v) : "l"(p) : "memory");
    return v;
}
__device__ __forceinline__ void st_release(unsigned* p, unsigned v) {
    asm volatile("st.global.release.gpu.u32 [%0], %1;" :: "l"(p), "r"(v) : "memory");
}

// ---------------------------------------------------------------------------
// CAVI kernel: persistent grid, 1 column per thread, all state in registers.
// Per (k,l) step: local flash-style softmax partial (m, S) per CTA, ONE
// grid barrier (monotonic counter + phase flag), parallel combine by warp0.
// ---------------------------------------------------------------------------
__global__ void __launch_bounds__(NT, 1)
cavi_kernel(const float* __restrict__ mzz, const float* __restrict__ mw_in,
            const float* __restrict__ a_in, const float* __restrict__ tau_p,
            const float* __restrict__ tau0, const float* __restrict__ pi,
            float* __restrict__ out_mw, float* __restrict__ out_vw,
            float* __restrict__ out_a) {
    __shared__ float sWm[NWARP];
    __shared__ float sWs[NWARP];
    __shared__ float2 sMT;

    const int tid = threadIdx.x;
    const int w = tid >> 5;
    const int lane = tid & 31;
    const int cta = blockIdx.x;
    const int col = cta * CH + tid;
    const bool active = (tid < CH) && (col < PP);
    const float tau = __ldg(tau_p);

    // W[j] = sum_l mw[l,j,col]*a[l,j,col] for own column (registers)
    float W[ZZ];
#pragma unroll
    for (int j = 0; j < ZZ; j++) W[j] = 0.f;
    if (active) {
#pragma unroll
        for (int j = 0; j < ZZ; j++) {
            float s = 0.f;
#pragma unroll
            for (int l = 0; l < LL; l++)
                s += __ldg(&mw_in[((size_t)l * ZZ + j) * PP + col]) *
                     __ldg(&a_in[((size_t)l * ZZ + j) * PP + col]);
            W[j] = s;
        }
    }

    int b = 0;  // global step index (0..199)
    for (int k = 0; k < ZZ; k++) {
        const float Ez = __ldg(&mzz[k * ZZ + k]);
        const float invEz = 1.f / Ez;

        // Prologue (register-only): RtZk, D, log pi for own column
        float RtZk = 0.f, D = 0.f, lp = 0.f;
        if (active) {
            float acc = g_ZtX[(size_t)k * PP + col];
            float wkv = 0.f;
#pragma unroll
            for (int j = 0; j < ZZ; j++) {
                float mj = __ldg(&mzz[k * ZZ + j]);
                if (j == k) wkv = W[j];
                else acc -= mj * W[j];
            }
            RtZk = acc;
            D = acc - Ez * wkv;
            lp = __logf(__ldg(&pi[(size_t)k * PP + col]));
        }

        const float s2 = 1.f / (Ez * tau);
        const float l_s2 = __logf(s2);

        const size_t lst = (size_t)ZZ * PP;
        const float* pmw = mw_in + (size_t)k * PP + col;
        const float* pa = a_in + (size_t)k * PP + col;
        float mw_nxt = 0.f, a_nxt = 0.f;
        if (active) { mw_nxt = __ldg(pmw); a_nxt = __ldg(pa); }

        for (int l = 0; l < LL; l++, b++) {
            const float t0 = __ldg(&tau0[l * ZZ + k]);
            const float s0inv = 1.f / t0;
            const float s2p = s2 + s0inv;
            const float c0 = 0.5f * (l_s2 - __logf(s2p));
            const float c1 = 0.5f * (s0inv / s2p) * (tau * invEz);
            const float varn = 1.f / (tau * Ez + t0);
            const float tv = tau * varn;

            const float mwv = mw_nxt, av = a_nxt;
            if (l + 1 < LL && active) {  // prefetch next l (hides DRAM latency)
                mw_nxt = __ldg(pmw + (size_t)(l + 1) * lst);
                a_nxt = __ldg(pa + (size_t)(l + 1) * lst);
            }

            float E = 0.f, s = -INFINITY;
            if (active) {
                E = fmaf(Ez, mwv * av, D);
                s = fmaf(c1 * E, E, lp + c0);
            }

            // warp-local flash partial: m_w, e = exp(s - m_w), S_w
            float m_w = s;
#pragma unroll
            for (int o = 16; o; o >>= 1)
                m_w = fmaxf(m_w, __shfl_xor_sync(0xffffffffu, m_w, o));
            float e = active ? __expf(s - m_w) : 0.f;
            float S_w = e;
#pragma unroll
            for (int o = 16; o; o >>= 1)
                S_w += __shfl_xor_sync(0xffffffffu, S_w, o);
            if (!lane) { sWm[w] = m_w; sWs[w] = S_w; }
            __syncthreads();  // bar1

            if (w == 0) {
                // CTA partial (m_r, S_r) from the 11 warp partials
                float mj = (lane < NWARP) ? sWm[lane] : -INFINITY;
                float Sj = (lane < NWARP) ? sWs[lane] : 0.f;
                float m_r = mj;
#pragma unroll
                for (int o = 16; o; o >>= 1)
                    m_r = fmaxf(m_r, __shfl_xor_sync(0xffffffffu, m_r, o));
                float t = (lane < NWARP && Sj > 0.f) ? Sj * __expf(mj - m_r) : 0.f;
#pragma unroll
                for (int o = 16; o; o >>= 1)
                    t += __shfl_xor_sync(0xffffffffu, t, o);

                // publish partial + grid barrier arrive (lane 0)
                if (!lane) {
                    g_part[b & 1][cta] = make_float2(m_r, t);
                    __threadfence();
                    unsigned old = atomicAdd(&g_cnt, 1u);
                    if (old == (unsigned)NC * (unsigned)(b + 1) - 1u)
                        st_release(&g_phase, (unsigned)(b + 1));
                }
                // spin (uniform address, whole warp)
                while (ld_acquire(&g_phase) < (unsigned)(b + 1)) {}

                // combine the 148 CTA partials in parallel
                const float2* gp = g_part[b & 1];
                float2 pj[5];
                float M = -INFINITY;
#pragma unroll
                for (int it = 0; it < 5; it++) {
                    int j = lane + it * 32;
                    pj[it] = (j < NC) ? gp[j] : make_float2(-INFINITY, 0.f);
                    M = fmaxf(M, pj[it].x);
                }
#pragma unroll
                for (int o = 16; o; o >>= 1)
                    M = fmaxf(M, __shfl_xor_sync(0xffffffffu, M, o));
                float T = 0.f;
#pragma unroll
                for (int it = 0; it < 5; it++)
                    if (pj[it].y > 0.f) T += pj[it].y * __expf(pj[it].x - M);
#pragma unroll
                for (int o = 16; o; o >>= 1)
                    T += __shfl_xor_sync(0xffffffffu, T, o);
                if (!lane) sMT = make_float2(M, T);
            }
            __syncthreads();  // bar2

            const float M = sMT.x, T = sMT.y;
            // per-warp uniform scale = exp(m_w - M)/T (lane0 + broadcast)
            float sc = 0.f;
            if (!lane) sc = (m_w > -INFINITY) ? __expf(m_w - M) / T : 0.f;
            sc = __shfl_sync(0xffffffffu, sc, 0);

            if (active) {
                float an = e * sc;
                float mn = tv * E;
                out_mw[(size_t)(l * ZZ + k) * PP + col] = mn;
                out_a[(size_t)(l * ZZ + k) * PP + col] = an;
                D = fmaf(-Ez, mn * an, E);  // D_new = E - Ez*mean*alpha
            }
            if (cta == 0 && tid == 0) out_vw[l * ZZ + k] = varn;
        }

        // epilogue: W[k] = (RtZk - D)/Ez (register select, no dynamic index)
        if (active) {
            float wkf = (RtZk - D) * invEz;
#pragma unroll
            for (int j = 0; j < ZZ; j++)
                if (j == k) W[j] = wkf;
        }
    }
}

// ---------------------------------------------------------------------------
// Launch
// ---------------------------------------------------------------------------
extern "C" void kernel_launch(void* const* d_in, const int* in_sizes, int n_in,
                              void* d_out, int out_size) {
    const float* data = (const float*)d_in[0];
    const float* mz = (const float*)d_in[1];
    const float* mzz = (const float*)d_in[2];
    const float* mw = (const float*)d_in[3];
    // d_in[4] = var_w (unused: fully overwritten)
    const float* alpha = (const float*)d_in[5];
    const float* tau = (const float*)d_in[6];
    const float* tau0 = (const float*)d_in[7];
    const float* pi = (const float*)d_in[8];

    float* out = (float*)d_out;
    float* out_mw = out;                              // [L,Z,P]
    float* out_vw = out + (size_t)LL * ZZ * PP;       // [L,Z]
    float* out_a = out_vw + LL * ZZ;                  // [L,Z,P]

    reset_kernel<<<1, 1>>>();

    dim3 g2((PP / 4 + 255) / 256, NCH);
    ztx_partial_kernel<<<g2, 256>>>(data, mz);
    ztx_reduce_kernel<<<(ZZ * PP + 255) / 256, 256>>>();

    cavi_kernel<<<NC, NT>>>(mzz, mw, alpha, tau, tau0, pi,
                            out_mw, out_vw, out_a);
}